// round 1
// baseline (speedup 1.0000x reference)
#include <cuda_runtime.h>

#define NN 4096
#define H 5
#define NSLAB 148
#define ROWS_PER_SLAB 28   // 148*28 = 4144 >= 4096 (ragged tail handled)
#define TPB 256            // each thread handles 4 columns (float4) -> 1024 cols/block
#define GX 4               // 4 column blocks * 1024 = 4096 columns

// Scratch (no allocation allowed in kernel_launch)
__device__ float g_Z[NN];
__device__ float g_part[(size_t)NSLAB * NN];

// ---------------------------------------------------------------------------
// Per-element 1->H->1 ReLU MLP. acc starts at b2 so the output bias is free.
// ---------------------------------------------------------------------------
__device__ __forceinline__ float tiny_mlp(float x,
                                          const float w1[H], const float b1[H],
                                          const float w2[H], float b2) {
    float a = b2;
#pragma unroll
    for (int h = 0; h < H; h++) {
        float t = fmaf(w1[h], x, b1[h]);
        a = fmaf(w2[h], fmaxf(t, 0.0f), a);
    }
    return fmaxf(a, 0.0f);
}

// ---------------------------------------------------------------------------
// Kernel 1: Z[i] = mlp_z(Zj[i])
// ---------------------------------------------------------------------------
__global__ void z_kernel(const float* __restrict__ Zj,
                         const float* __restrict__ zw1, const float* __restrict__ zb1,
                         const float* __restrict__ zw2, const float* __restrict__ zb2) {
    int i = blockIdx.x * blockDim.x + threadIdx.x;
    if (i >= NN) return;
    float w1[H], b1[H], w2[H];
#pragma unroll
    for (int h = 0; h < H; h++) { w1[h] = zw1[h]; b1[h] = zb1[h]; w2[h] = zw2[h]; }
    float b2 = zb2[0];
    g_Z[i] = tiny_mlp(Zj[i], w1, b1, w2, b2);
}

// ---------------------------------------------------------------------------
// Kernel 2: partial[slab][j] = sum_{i in slab} Z[i] * mlp_r(Rij[i][j])
// Grid: (GX, NSLAB). Thread t in block bx owns float4 column group
// col4 = bx*TPB + t  (4 consecutive fp32 columns -> LDG.128, fully coalesced).
// ---------------------------------------------------------------------------
__global__ void __launch_bounds__(TPB)
r_kernel(const float* __restrict__ Rij,
         const float* __restrict__ rw1, const float* __restrict__ rb1,
         const float* __restrict__ rw2, const float* __restrict__ rb2) {
    __shared__ float zsh[ROWS_PER_SLAB];

    const int slab = blockIdx.y;
    const int row0 = slab * ROWS_PER_SLAB;
    int rows = NN - row0;
    if (rows > ROWS_PER_SLAB) rows = ROWS_PER_SLAB;
    if (rows < 0) rows = 0;

    // Stage this slab's Z values in smem (broadcast reads later)
    for (int r = threadIdx.x; r < ROWS_PER_SLAB; r += TPB)
        zsh[r] = (row0 + r < NN) ? g_Z[row0 + r] : 0.0f;
    __syncthreads();

    float w1[H], b1[H], w2[H];
#pragma unroll
    for (int h = 0; h < H; h++) { w1[h] = rw1[h]; b1[h] = rb1[h]; w2[h] = rw2[h]; }
    const float b2 = rb2[0];

    const int col4 = blockIdx.x * TPB + threadIdx.x;      // 0..1023
    const float4* __restrict__ R4 = (const float4*)Rij;    // row stride NN/4

    float ax = 0.0f, ay = 0.0f, az = 0.0f, aw = 0.0f;

#pragma unroll 4
    for (int r = 0; r < rows; r++) {
        float4 v = R4[(size_t)(row0 + r) * (NN / 4) + col4];
        float zi = zsh[r];
        ax = fmaf(zi, tiny_mlp(v.x, w1, b1, w2, b2), ax);
        ay = fmaf(zi, tiny_mlp(v.y, w1, b1, w2, b2), ay);
        az = fmaf(zi, tiny_mlp(v.z, w1, b1, w2, b2), az);
        aw = fmaf(zi, tiny_mlp(v.w, w1, b1, w2, b2), aw);
    }

    float4 outv; outv.x = ax; outv.y = ay; outv.z = az; outv.w = aw;
    ((float4*)(g_part + (size_t)slab * NN))[col4] = outv;
}

// ---------------------------------------------------------------------------
// Kernel 3: out[j] = sum_slab partial[slab][j]   (fixed order -> deterministic)
// ---------------------------------------------------------------------------
__global__ void reduce_kernel(float* __restrict__ out) {
    int j4 = blockIdx.x * blockDim.x + threadIdx.x;   // 0..1023 float4 groups
    if (j4 >= NN / 4) return;
    float sx = 0.0f, sy = 0.0f, sz = 0.0f, sw = 0.0f;
#pragma unroll 4
    for (int s = 0; s < NSLAB; s++) {
        float4 v = ((const float4*)(g_part + (size_t)s * NN))[j4];
        sx += v.x; sy += v.y; sz += v.z; sw += v.w;
    }
    float4 o; o.x = sx; o.y = sy; o.z = sz; o.w = sw;
    ((float4*)out)[j4] = o;
}

// ---------------------------------------------------------------------------
extern "C" void kernel_launch(void* const* d_in, const int* in_sizes, int n_in,
                              void* d_out, int out_size) {
    const float* Rij = (const float*)d_in[0];
    const float* Zj  = (const float*)d_in[1];
    const float* rw1 = (const float*)d_in[2];
    const float* rb1 = (const float*)d_in[3];
    const float* rw2 = (const float*)d_in[4];
    const float* rb2 = (const float*)d_in[5];
    const float* zw1 = (const float*)d_in[6];
    const float* zb1 = (const float*)d_in[7];
    const float* zw2 = (const float*)d_in[8];
    const float* zb2 = (const float*)d_in[9];

    z_kernel<<<NN / 256, 256>>>(Zj, zw1, zb1, zw2, zb2);
    r_kernel<<<dim3(GX, NSLAB), TPB>>>(Rij, rw1, rb1, rw2, rb2);
    reduce_kernel<<<NN / 4 / 256, 256>>>((float*)d_out);
}

// round 3
// speedup vs baseline: 1.5476x; 1.5476x over previous
#include <cuda_runtime.h>

#define NN 4096
#define H 5
#define NSLAB 148
#define ROWS_PER_SLAB 28   // 148*28 = 4144 >= 4096 (ragged tail handled)
#define TPB 256            // each thread handles 4 columns (float4) -> 1024 cols/block
#define GX 4               // 4 column blocks * 1024 = 4096 columns

// Scratch (no allocation allowed in kernel_launch)
__device__ float g_part[(size_t)NSLAB * NN];

// ---------------------------------------------------------------------------
// Packed fp32x2 FMA (Blackwell sm_100+). Bit-identical to two scalar fmaf.
// The mov.b64 pack/unpack typically dissolves into aligned register pairs.
// ---------------------------------------------------------------------------
__device__ __forceinline__ float2 ffma2(float2 a, float2 b, float2 c) {
    float2 d;
    asm("{\n\t"
        ".reg .b64 ra, rb, rc, rd;\n\t"
        "mov.b64 ra, {%2,%3};\n\t"
        "mov.b64 rb, {%4,%5};\n\t"
        "mov.b64 rc, {%6,%7};\n\t"
        "fma.rn.f32x2 rd, ra, rb, rc;\n\t"
        "mov.b64 {%0,%1}, rd;\n\t"
        "}"
        : "=f"(d.x), "=f"(d.y)
        : "f"(a.x), "f"(a.y), "f"(b.x), "f"(b.y), "f"(c.x), "f"(c.y));
    return d;
}

// Scalar tiny MLP (used for the small Z vector only)
__device__ __forceinline__ float tiny_mlp(float x,
                                          const float* __restrict__ w1,
                                          const float* __restrict__ b1,
                                          const float* __restrict__ w2, float b2) {
    float a = b2;
#pragma unroll
    for (int h = 0; h < H; h++) {
        float t = fmaf(__ldg(&w1[h]), x, __ldg(&b1[h]));
        a = fmaf(__ldg(&w2[h]), fmaxf(t, 0.0f), a);
    }
    return fmaxf(a, 0.0f);
}

// Packed pair MLP with final relu. w1p/b1p/w2p are broadcast-packed weights.
__device__ __forceinline__ float2 mlp_pair(float2 p,
                                           const float2* w1p, const float2* b1p,
                                           const float2* w2p, float2 b2p) {
    float2 a = b2p;
#pragma unroll
    for (int h = 0; h < H; h++) {
        float2 t = ffma2(w1p[h], p, b1p[h]);
        t.x = fmaxf(t.x, 0.0f);
        t.y = fmaxf(t.y, 0.0f);
        a = ffma2(w2p[h], t, a);
    }
    a.x = fmaxf(a.x, 0.0f);
    a.y = fmaxf(a.y, 0.0f);
    return a;
}

// ---------------------------------------------------------------------------
// Main kernel: partial[slab][j] = sum_{i in slab} Z[i] * mlp_r(Rij[i][j])
// Z is computed in-block (fused) from Zj. Grid (GX, NSLAB), TPB threads,
// float4 column groups -> fully coalesced LDG.128 streaming loads.
// ---------------------------------------------------------------------------
__global__ void __launch_bounds__(TPB)
r_kernel(const float* __restrict__ Rij, const float* __restrict__ Zj,
         const float* __restrict__ rw1, const float* __restrict__ rb1,
         const float* __restrict__ rw2, const float* __restrict__ rb2,
         const float* __restrict__ zw1, const float* __restrict__ zb1,
         const float* __restrict__ zw2, const float* __restrict__ zb2) {
    __shared__ float zsh[ROWS_PER_SLAB];

    const int slab = blockIdx.y;
    const int row0 = slab * ROWS_PER_SLAB;
    int rows = NN - row0;
    if (rows > ROWS_PER_SLAB) rows = ROWS_PER_SLAB;
    if (rows < 0) rows = 0;

    // Fused Z computation: threads 0..rows-1 each produce one Z value.
    if (threadIdx.x < ROWS_PER_SLAB) {
        int r = threadIdx.x;
        float z = 0.0f;
        if (r < rows)
            z = tiny_mlp(Zj[row0 + r], zw1, zb1, zw2, __ldg(&zb2[0]));
        zsh[r] = z;
    }
    __syncthreads();

    // Broadcast-packed R weights
    float2 w1p[H], b1p[H], w2p[H];
#pragma unroll
    for (int h = 0; h < H; h++) {
        float a = __ldg(&rw1[h]), b = __ldg(&rb1[h]), c = __ldg(&rw2[h]);
        w1p[h] = make_float2(a, a);
        b1p[h] = make_float2(b, b);
        w2p[h] = make_float2(c, c);
    }
    const float b2 = __ldg(&rb2[0]);
    const float2 b2p = make_float2(b2, b2);

    const int col4 = blockIdx.x * TPB + threadIdx.x;       // 0..1023
    const float4* __restrict__ R4 = (const float4*)Rij;     // row stride NN/4

    float2 acc0 = make_float2(0.0f, 0.0f);
    float2 acc1 = make_float2(0.0f, 0.0f);

#pragma unroll 4
    for (int r = 0; r < rows; r++) {
        float4 v = __ldcs(&R4[(size_t)(row0 + r) * (NN / 4) + col4]);
        float zi = zsh[r];
        float2 zp = make_float2(zi, zi);
        float2 y0 = mlp_pair(make_float2(v.x, v.y), w1p, b1p, w2p, b2p);
        float2 y1 = mlp_pair(make_float2(v.z, v.w), w1p, b1p, w2p, b2p);
        acc0 = ffma2(zp, y0, acc0);
        acc1 = ffma2(zp, y1, acc1);
    }

    float4 outv;
    outv.x = acc0.x; outv.y = acc0.y; outv.z = acc1.x; outv.w = acc1.y;
    ((float4*)(g_part + (size_t)slab * NN))[col4] = outv;
}

// ---------------------------------------------------------------------------
// Reduce: one warp per float4 column group (1024 warps = 128 blocks).
// Lane-strided slab partials + shfl tree: fixed order -> deterministic.
// ---------------------------------------------------------------------------
__global__ void __launch_bounds__(TPB)
reduce_kernel(float* __restrict__ out) {
    const int g = blockIdx.x * (TPB / 32) + (threadIdx.x >> 5); // 0..1023
    const int lane = threadIdx.x & 31;

    float sx = 0.0f, sy = 0.0f, sz = 0.0f, sw = 0.0f;
    for (int s = lane; s < NSLAB; s += 32) {
        float4 v = ((const float4*)(g_part + (size_t)s * NN))[g];
        sx += v.x; sy += v.y; sz += v.z; sw += v.w;
    }
#pragma unroll
    for (int off = 16; off > 0; off >>= 1) {
        sx += __shfl_down_sync(0xFFFFFFFFu, sx, off);
        sy += __shfl_down_sync(0xFFFFFFFFu, sy, off);
        sz += __shfl_down_sync(0xFFFFFFFFu, sz, off);
        sw += __shfl_down_sync(0xFFFFFFFFu, sw, off);
    }
    if (lane == 0) {
        float4 o; o.x = sx; o.y = sy; o.z = sz; o.w = sw;
        ((float4*)out)[g] = o;
    }
}

// ---------------------------------------------------------------------------
extern "C" void kernel_launch(void* const* d_in, const int* in_sizes, int n_in,
                              void* d_out, int out_size) {
    const float* Rij = (const float*)d_in[0];
    const float* Zj  = (const float*)d_in[1];
    const float* rw1 = (const float*)d_in[2];
    const float* rb1 = (const float*)d_in[3];
    const float* rw2 = (const float*)d_in[4];
    const float* rb2 = (const float*)d_in[5];
    const float* zw1 = (const float*)d_in[6];
    const float* zb1 = (const float*)d_in[7];
    const float* zw2 = (const float*)d_in[8];
    const float* zb2 = (const float*)d_in[9];

    r_kernel<<<dim3(GX, NSLAB), TPB>>>(Rij, Zj, rw1, rb1, rw2, rb2,
                                       zw1, zb1, zw2, zb2);
    reduce_kernel<<<NN / 4 / (TPB / 32), TPB>>>((float*)d_out);
}

// round 4
// speedup vs baseline: 1.6899x; 1.0920x over previous
#include <cuda_runtime.h>

#define NN 4096
#define H 5
#define NSLAB 148
#define ROWS_PER_SLAB 28   // 148*28 = 4144 >= 4096 (ragged tail handled)
#define TPB 256            // each thread handles 4 columns (float4) -> 1024 cols/block
#define GX 4               // 4 column blocks * 1024 = 4096 columns

// Scratch (no allocation allowed in kernel_launch)
__device__ float g_part[(size_t)NSLAB * NN];

// ---------------------------------------------------------------------------
// Packed fp32x2 FMA (Blackwell sm_100+). Bit-identical to two scalar fmaf.
// ---------------------------------------------------------------------------
__device__ __forceinline__ float2 ffma2(float2 a, float2 b, float2 c) {
    float2 d;
    asm("{\n\t"
        ".reg .b64 ra, rb, rc, rd;\n\t"
        "mov.b64 ra, {%2,%3};\n\t"
        "mov.b64 rb, {%4,%5};\n\t"
        "mov.b64 rc, {%6,%7};\n\t"
        "fma.rn.f32x2 rd, ra, rb, rc;\n\t"
        "mov.b64 {%0,%1}, rd;\n\t"
        "}"
        : "=f"(d.x), "=f"(d.y)
        : "f"(a.x), "f"(a.y), "f"(b.x), "f"(b.y), "f"(c.x), "f"(c.y));
    return d;
}

// Scalar tiny MLP (used for the small Z vector only)
__device__ __forceinline__ float tiny_mlp(float x,
                                          const float* __restrict__ w1,
                                          const float* __restrict__ b1,
                                          const float* __restrict__ w2, float b2) {
    float a = b2;
#pragma unroll
    for (int h = 0; h < H; h++) {
        float t = fmaf(__ldg(&w1[h]), x, __ldg(&b1[h]));
        a = fmaf(__ldg(&w2[h]), fmaxf(t, 0.0f), a);
    }
    return fmaxf(a, 0.0f);
}

// Packed pair MLP with final relu. w1p/b1p/w2p are broadcast-packed weights.
__device__ __forceinline__ float2 mlp_pair(float2 p,
                                           const float2* w1p, const float2* b1p,
                                           const float2* w2p, float2 b2p) {
    float2 a = b2p;
#pragma unroll
    for (int h = 0; h < H; h++) {
        float2 t = ffma2(w1p[h], p, b1p[h]);
        t.x = fmaxf(t.x, 0.0f);
        t.y = fmaxf(t.y, 0.0f);
        a = ffma2(w2p[h], t, a);
    }
    a.x = fmaxf(a.x, 0.0f);
    a.y = fmaxf(a.y, 0.0f);
    return a;
}

// ---------------------------------------------------------------------------
// Main kernel: partial[slab][j] = sum_{i in slab} Z[i] * mlp_r(Rij[i][j])
// Z is computed in-block (fused) from Zj. Grid (GX, NSLAB), TPB threads,
// float4 column groups -> fully coalesced LDG.128 streaming loads.
// ---------------------------------------------------------------------------
__global__ void __launch_bounds__(TPB)
r_kernel(const float* __restrict__ Rij, const float* __restrict__ Zj,
         const float* __restrict__ rw1, const float* __restrict__ rb1,
         const float* __restrict__ rw2, const float* __restrict__ rb2,
         const float* __restrict__ zw1, const float* __restrict__ zb1,
         const float* __restrict__ zw2, const float* __restrict__ zb2) {
    __shared__ float zsh[ROWS_PER_SLAB];

    const int slab = blockIdx.y;
    const int row0 = slab * ROWS_PER_SLAB;
    int rows = NN - row0;
    if (rows > ROWS_PER_SLAB) rows = ROWS_PER_SLAB;
    if (rows < 0) rows = 0;

    // Fused Z computation: threads 0..rows-1 each produce one Z value.
    if (threadIdx.x < ROWS_PER_SLAB) {
        int r = threadIdx.x;
        float z = 0.0f;
        if (r < rows)
            z = tiny_mlp(Zj[row0 + r], zw1, zb1, zw2, __ldg(&zb2[0]));
        zsh[r] = z;
    }
    __syncthreads();

    // Broadcast-packed R weights
    float2 w1p[H], b1p[H], w2p[H];
#pragma unroll
    for (int h = 0; h < H; h++) {
        float a = __ldg(&rw1[h]), b = __ldg(&rb1[h]), c = __ldg(&rw2[h]);
        w1p[h] = make_float2(a, a);
        b1p[h] = make_float2(b, b);
        w2p[h] = make_float2(c, c);
    }
    const float b2 = __ldg(&rb2[0]);
    const float2 b2p = make_float2(b2, b2);

    const int col4 = blockIdx.x * TPB + threadIdx.x;       // 0..1023
    const float4* __restrict__ R4 = (const float4*)Rij;     // row stride NN/4

    float2 acc0 = make_float2(0.0f, 0.0f);
    float2 acc1 = make_float2(0.0f, 0.0f);

    // 28 = 4 x 7: unroll 7 front-batches 7 LDG.128 -> MLP_p1 ~ 7
#pragma unroll 7
    for (int r = 0; r < rows; r++) {
        float4 v = __ldcs(&R4[(size_t)(row0 + r) * (NN / 4) + col4]);
        float zi = zsh[r];
        float2 zp = make_float2(zi, zi);
        float2 y0 = mlp_pair(make_float2(v.x, v.y), w1p, b1p, w2p, b2p);
        float2 y1 = mlp_pair(make_float2(v.z, v.w), w1p, b1p, w2p, b2p);
        acc0 = ffma2(zp, y0, acc0);
        acc1 = ffma2(zp, y1, acc1);
    }

    float4 outv;
    outv.x = acc0.x; outv.y = acc0.y; outv.z = acc1.x; outv.w = acc1.y;
    ((float4*)(g_part + (size_t)slab * NN))[col4] = outv;
}

// ---------------------------------------------------------------------------
// Reduce: 128 blocks x 256 threads. Block owns 8 float4 groups (128 B — one
// full cache line per slab-row segment). tx = group (coalesced within warp),
// ty = slab stride. Deterministic smem tree over ty.
// ---------------------------------------------------------------------------
__global__ void __launch_bounds__(TPB)
reduce_kernel(float* __restrict__ out) {
    __shared__ float4 sred[32][8];
    const int tx = threadIdx.x & 7;        // float4 group within block
    const int ty = threadIdx.x >> 3;       // 0..31: slab stride lane
    const int g  = blockIdx.x * 8 + tx;    // global float4 group 0..1023

    float4 acc = make_float4(0.0f, 0.0f, 0.0f, 0.0f);
    for (int s = ty; s < NSLAB; s += 32) {
        float4 v = ((const float4*)(g_part + (size_t)s * NN))[g];
        acc.x += v.x; acc.y += v.y; acc.z += v.z; acc.w += v.w;
    }
    sred[ty][tx] = acc;
    __syncthreads();

#pragma unroll
    for (int off = 16; off > 0; off >>= 1) {
        if (ty < off) {
            float4 o = sred[ty + off][tx];
            acc.x += o.x; acc.y += o.y; acc.z += o.z; acc.w += o.w;
            sred[ty][tx] = acc;
        }
        __syncthreads();
    }

    if (ty == 0)
        ((float4*)out)[g] = acc;
}

// ---------------------------------------------------------------------------
extern "C" void kernel_launch(void* const* d_in, const int* in_sizes, int n_in,
                              void* d_out, int out_size) {
    const float* Rij = (const float*)d_in[0];
    const float* Zj  = (const float*)d_in[1];
    const float* rw1 = (const float*)d_in[2];
    const float* rb1 = (const float*)d_in[3];
    const float* rw2 = (const float*)d_in[4];
    const float* rb2 = (const float*)d_in[5];
    const float* zw1 = (const float*)d_in[6];
    const float* zb1 = (const float*)d_in[7];
    const float* zw2 = (const float*)d_in[8];
    const float* zb2 = (const float*)d_in[9];

    r_kernel<<<dim3(GX, NSLAB), TPB>>>(Rij, Zj, rw1, rb1, rw2, rb2,
                                       zw1, zb1, zw2, zb2);
    reduce_kernel<<<NN / 4 / 8, TPB>>>((float*)d_out);
}

// round 5
// speedup vs baseline: 1.7746x; 1.0501x over previous
#include <cuda_runtime.h>

#define NN 4096
#define H 5
#define NSLAB 148
#define ROWS_PER_SLAB 28   // 148*28 = 4144 >= 4096 (ragged tail handled)
#define TPB 256            // each thread handles 4 columns (float4) -> 1024 cols/block
#define GX 4               // 4 column blocks * 1024 = 4096 columns

// Scratch (no allocation allowed in kernel_launch)
__device__ float g_part[(size_t)NSLAB * NN];

// ---------------------------------------------------------------------------
// Packed fp32x2 FMA (Blackwell sm_100+). Bit-identical to two scalar fmaf.
// ---------------------------------------------------------------------------
__device__ __forceinline__ float2 ffma2(float2 a, float2 b, float2 c) {
    float2 d;
    asm("{\n\t"
        ".reg .b64 ra, rb, rc, rd;\n\t"
        "mov.b64 ra, {%2,%3};\n\t"
        "mov.b64 rb, {%4,%5};\n\t"
        "mov.b64 rc, {%6,%7};\n\t"
        "fma.rn.f32x2 rd, ra, rb, rc;\n\t"
        "mov.b64 {%0,%1}, rd;\n\t"
        "}"
        : "=f"(d.x), "=f"(d.y)
        : "f"(a.x), "f"(a.y), "f"(b.x), "f"(b.y), "f"(c.x), "f"(c.y));
    return d;
}

// Scalar tiny MLP (used for the small Z vector only)
__device__ __forceinline__ float tiny_mlp(float x,
                                          const float* __restrict__ w1,
                                          const float* __restrict__ b1,
                                          const float* __restrict__ w2, float b2) {
    float a = b2;
#pragma unroll
    for (int h = 0; h < H; h++) {
        float t = fmaf(__ldg(&w1[h]), x, __ldg(&b1[h]));
        a = fmaf(__ldg(&w2[h]), fmaxf(t, 0.0f), a);
    }
    return fmaxf(a, 0.0f);
}

// Packed pair MLP with final relu. w1p/b1p/w2p are broadcast-packed weights.
__device__ __forceinline__ float2 mlp_pair(float2 p,
                                           const float2* w1p, const float2* b1p,
                                           const float2* w2p, float2 b2p) {
    float2 a = b2p;
#pragma unroll
    for (int h = 0; h < H; h++) {
        float2 t = ffma2(w1p[h], p, b1p[h]);
        t.x = fmaxf(t.x, 0.0f);
        t.y = fmaxf(t.y, 0.0f);
        a = ffma2(w2p[h], t, a);
    }
    a.x = fmaxf(a.x, 0.0f);
    a.y = fmaxf(a.y, 0.0f);
    return a;
}

// ---------------------------------------------------------------------------
// Main kernel: partial[slab][j] = sum_{i in slab} Z[i] * mlp_r(Rij[i][j])
// (unchanged from R4 — measured ~85% of HBM roofline)
// ---------------------------------------------------------------------------
__global__ void __launch_bounds__(TPB)
r_kernel(const float* __restrict__ Rij, const float* __restrict__ Zj,
         const float* __restrict__ rw1, const float* __restrict__ rb1,
         const float* __restrict__ rw2, const float* __restrict__ rb2,
         const float* __restrict__ zw1, const float* __restrict__ zb1,
         const float* __restrict__ zw2, const float* __restrict__ zb2) {
    __shared__ float zsh[ROWS_PER_SLAB];

    const int slab = blockIdx.y;
    const int row0 = slab * ROWS_PER_SLAB;
    int rows = NN - row0;
    if (rows > ROWS_PER_SLAB) rows = ROWS_PER_SLAB;
    if (rows < 0) rows = 0;

    // Fused Z computation: threads 0..rows-1 each produce one Z value.
    if (threadIdx.x < ROWS_PER_SLAB) {
        int r = threadIdx.x;
        float z = 0.0f;
        if (r < rows)
            z = tiny_mlp(Zj[row0 + r], zw1, zb1, zw2, __ldg(&zb2[0]));
        zsh[r] = z;
    }
    __syncthreads();

    // Broadcast-packed R weights
    float2 w1p[H], b1p[H], w2p[H];
#pragma unroll
    for (int h = 0; h < H; h++) {
        float a = __ldg(&rw1[h]), b = __ldg(&rb1[h]), c = __ldg(&rw2[h]);
        w1p[h] = make_float2(a, a);
        b1p[h] = make_float2(b, b);
        w2p[h] = make_float2(c, c);
    }
    const float b2 = __ldg(&rb2[0]);
    const float2 b2p = make_float2(b2, b2);

    const int col4 = blockIdx.x * TPB + threadIdx.x;       // 0..1023
    const float4* __restrict__ R4 = (const float4*)Rij;     // row stride NN/4

    float2 acc0 = make_float2(0.0f, 0.0f);
    float2 acc1 = make_float2(0.0f, 0.0f);

#pragma unroll 7
    for (int r = 0; r < rows; r++) {
        float4 v = __ldcs(&R4[(size_t)(row0 + r) * (NN / 4) + col4]);
        float zi = zsh[r];
        float2 zp = make_float2(zi, zi);
        float2 y0 = mlp_pair(make_float2(v.x, v.y), w1p, b1p, w2p, b2p);
        float2 y1 = mlp_pair(make_float2(v.z, v.w), w1p, b1p, w2p, b2p);
        acc0 = ffma2(zp, y0, acc0);
        acc1 = ffma2(zp, y1, acc1);
    }

    float4 outv;
    outv.x = acc0.x; outv.y = acc0.y; outv.z = acc1.x; outv.w = acc1.y;
    ((float4*)(g_part + (size_t)slab * NN))[col4] = outv;
}

// ---------------------------------------------------------------------------
// Reduce v3: 128 blocks x 256 threads. Block = 32 columns x 8 slab-lanes.
// Warp load = 32 consecutive floats (one full 128B line). Each lane issues
// ~18-19 INDEPENDENT loads -> ~18KB in flight per SM -> chip BW >> demand.
// Two-register accumulation relaxes the FADD chain. Fixed-order finish.
// ---------------------------------------------------------------------------
__global__ void __launch_bounds__(256)
reduce_kernel(float* __restrict__ out) {
    __shared__ float sred[8][32];
    const int tx = threadIdx.x & 31;       // column within block
    const int ty = threadIdx.x >> 5;       // slab lane 0..7
    const int col = blockIdx.x * 32 + tx;  // global column 0..4095

    float a0 = 0.0f, a1 = 0.0f;
#pragma unroll
    for (int s = ty; s + 8 < NSLAB; s += 16) {
        a0 += g_part[(size_t)s * NN + col];
        a1 += g_part[(size_t)(s + 8) * NN + col];
    }
    // ragged tail of the s-loop (NSLAB=148: lanes 0..3 have one extra)
    {
        int s_last = ty + ((NSLAB - ty - 1) / 8) * 8;  // last valid slab for lane
        if (((NSLAB - ty + 7) / 8) & 1)                // odd trip count -> one left
            a0 += g_part[(size_t)s_last * NN + col];
    }
    sred[ty][tx] = a0 + a1;
    __syncthreads();

    if (ty == 0) {
        float s = sred[0][tx];
#pragma unroll
        for (int k = 1; k < 8; k++) s += sred[k][tx];
        out[col] = s;
    }
}

// ---------------------------------------------------------------------------
extern "C" void kernel_launch(void* const* d_in, const int* in_sizes, int n_in,
                              void* d_out, int out_size) {
    const float* Rij = (const float*)d_in[0];
    const float* Zj  = (const float*)d_in[1];
    const float* rw1 = (const float*)d_in[2];
    const float* rb1 = (const float*)d_in[3];
    const float* rw2 = (const float*)d_in[4];
    const float* rb2 = (const float*)d_in[5];
    const float* zw1 = (const float*)d_in[6];
    const float* zb1 = (const float*)d_in[7];
    const float* zw2 = (const float*)d_in[8];
    const float* zb2 = (const float*)d_in[9];

    r_kernel<<<dim3(GX, NSLAB), TPB>>>(Rij, Zj, rw1, rb1, rw2, rb2,
                                       zw1, zb1, zw2, zb2);
    reduce_kernel<<<NN / 32, 256>>>((float*)d_out);
}